// round 12
// baseline (speedup 1.0000x reference)
#include <cuda_runtime.h>
#include <cuda_fp16.h>
#include <math.h>

// ---------------- problem-size caps (compile-time scratch) ----------------
#define NMAX 100000
#define EMAX 1700000
#define CAP  96        // max padded degree (Poisson(16)+1; overflow prob ~1e-20)

// ---------------- device scratch (no allocations allowed) -----------------
__device__ __half  g_h1[NMAX * 128];   // layer1 features fp16 [N, 2*64]
__device__ __half  g_hfh[NMAX * 64];   // layer1 output (elu) fp16 [N, 64]
__device__ __half  g_h2[NMAX * 64];    // layer2 features fp16 [N, 2*32]
__device__ __half  g_W1h[128 * 128];
__device__ __half  g_W2h[64 * 64];
__device__ float2  g_wa1s[128], g_wa1d[128];   // folded W@att per k (h0,h1)
__device__ float2  g_wa2s[64],  g_wa2d[64];
__device__ float2  g_as1[NMAX], g_ad1[NMAX];
__device__ float2  g_as2[NMAX], g_ad2[NMAX];
__device__ int     g_cursor[NMAX];             // per-dst degree counter
__device__ int     g_adjp[NMAX * CAP];         // padded adjacency buckets

__device__ __forceinline__ float lrelu(float x) { return x > 0.f ? x : 0.2f * x; }

// ---- packed f32x2 helpers ----
__device__ __forceinline__ unsigned long long pack2(float lo, float hi) {
    unsigned long long r;
    asm("mov.b64 %0, {%1, %2};" : "=l"(r) : "f"(lo), "f"(hi));
    return r;
}
__device__ __forceinline__ void ffma2(unsigned long long& d, unsigned long long a,
                                      unsigned long long b) {
    asm("fma.rn.f32x2 %0, %1, %2, %0;" : "+l"(d) : "l"(a), "l"(b));
}
__device__ __forceinline__ float2 unpack2(unsigned long long v) {
    float2 r;
    asm("mov.b64 {%0, %1}, %2;" : "=f"(r.x), "=f"(r.y) : "l"(v));
    return r;
}

// ---------------- fold: wa = W @ att (per head) + fp16 weight conversion -------
__global__ void fold_kernel(const float* __restrict__ W1, const float* __restrict__ as1,
                            const float* __restrict__ ad1,
                            const float* __restrict__ W2, const float* __restrict__ as2,
                            const float* __restrict__ ad2,
                            __half* W1h, __half* W2h,
                            float2* wa1s, float2* wa1d, float2* wa2s, float2* wa2d) {
    int t = threadIdx.x;  // 256 threads, 1 block
    for (int i = t; i < 128 * 128; i += 256) W1h[i] = __float2half(W1[i]);
    for (int i = t; i < 64 * 64; i += 256)   W2h[i] = __float2half(W2[i]);
    if (t < 128) {
        float s0 = 0, s1 = 0, d0 = 0, d1 = 0;
        for (int c = 0; c < 64; c++) {
            float w0 = W1[t * 128 + c], w1 = W1[t * 128 + 64 + c];
            s0 = fmaf(w0, as1[c], s0);      s1 = fmaf(w1, as1[64 + c], s1);
            d0 = fmaf(w0, ad1[c], d0);      d1 = fmaf(w1, ad1[64 + c], d1);
        }
        wa1s[t] = make_float2(s0, s1); wa1d[t] = make_float2(d0, d1);
    }
    if (t < 64) {
        float s0 = 0, s1 = 0, d0 = 0, d1 = 0;
        for (int c = 0; c < 32; c++) {
            float w0 = W2[t * 64 + c], w1 = W2[t * 64 + 32 + c];
            s0 = fmaf(w0, as2[c], s0);      s1 = fmaf(w1, as2[32 + c], s1);
            d0 = fmaf(w0, ad2[c], d0);      d1 = fmaf(w1, ad2[32 + c], d1);
        }
        wa2s[t] = make_float2(s0, s1); wa2d[t] = make_float2(d0, d1);
    }
}

// ---------------- padded-bucket scatter ----------------
__global__ void scatter_kernel(const int* __restrict__ ei, int E, int N,
                               int* cursor, int* __restrict__ adjp) {
    int e = blockIdx.x * blockDim.x + threadIdx.x;
    int tot = E + N;
    if (e >= tot) return;
    int src, dst;
    if (e < E) { src = ei[e]; dst = ei[E + e]; }
    else       { src = e - E; dst = e - E; }
    int pos = atomicAdd(&cursor[dst], 1);
    if (pos < CAP) adjp[dst * CAP + pos] = src;
}

// ---------- fused GEMM1: fp32 x -> fp16 convert + HMMA + exact as1/ad1 ----------
__global__ __launch_bounds__(256, 2) void mma_gemm1_fused_kernel(
    const float* __restrict__ X, const __half* __restrict__ W,
    const float2* __restrict__ wa1s, const float2* __restrict__ wa1d,
    __half* __restrict__ C, float2* __restrict__ as, float2* __restrict__ ad, int n) {
    const int K = 128, M = 128, WN = 64, BM = 128;
    const int AS = K + 8, WS = M + 8, NB = WN / 8;
    extern __shared__ __half sm[];
    __half* As = sm;
    __half* Ws = sm + BM * AS;
    float4* sWa = (float4*)(Ws + K * WS);
    int tid = threadIdx.x;
    int lane = tid & 31;
    int row0 = blockIdx.x * BM;

    if (tid < 128) {
        float2 ws = wa1s[tid], wd = wa1d[tid];
        sWa[tid] = make_float4(ws.x, ws.y, wd.x, wd.y);
    }
    for (int i = tid; i < K * M / 8; i += 256) {
        int r = i / (M / 8), c = i % (M / 8);
        *(uint4*)(Ws + r * WS + c * 8) = *(const uint4*)(W + r * M + c * 8);
    }
    __syncthreads();

    const float4* X4 = (const float4*)X;
#pragma unroll
    for (int jj = 0; jj < BM * K / 8 / 256; jj++) {
        int i = tid + jj * 256;
        int r = i >> 4, c = i & 15;
        int row = row0 + r;
        float4 v0, v1;
        if (row < n) {
            v0 = X4[(size_t)row * 32 + c * 2];
            v1 = X4[(size_t)row * 32 + c * 2 + 1];
        } else {
            v0 = make_float4(0, 0, 0, 0); v1 = v0;
        }
        __half2 p0 = __floats2half2_rn(v0.x, v0.y), p1 = __floats2half2_rn(v0.z, v0.w);
        __half2 p2 = __floats2half2_rn(v1.x, v1.y), p3 = __floats2half2_rn(v1.z, v1.w);
        *(uint4*)(As + r * AS + c * 8) = make_uint4(
            *(unsigned*)&p0, *(unsigned*)&p1, *(unsigned*)&p2, *(unsigned*)&p3);

        float xs[8] = {v0.x, v0.y, v0.z, v0.w, v1.x, v1.y, v1.z, v1.w};
        float s0 = 0, s1 = 0, d0 = 0, d1 = 0;
        int k0 = c * 8;
#pragma unroll
        for (int e = 0; e < 8; e++) {
            float4 w = sWa[k0 + e];
            s0 = fmaf(xs[e], w.x, s0); s1 = fmaf(xs[e], w.y, s1);
            d0 = fmaf(xs[e], w.z, d0); d1 = fmaf(xs[e], w.w, d1);
        }
#pragma unroll
        for (int off = 8; off >= 1; off >>= 1) {
            s0 += __shfl_xor_sync(0xffffffffu, s0, off);
            s1 += __shfl_xor_sync(0xffffffffu, s1, off);
            d0 += __shfl_xor_sync(0xffffffffu, d0, off);
            d1 += __shfl_xor_sync(0xffffffffu, d1, off);
        }
        if ((lane & 15) == 0 && row < n) {
            as[row] = make_float2(s0, s1);
            ad[row] = make_float2(d0, d1);
        }
    }
    __syncthreads();

    int warp = tid >> 5;
    int wm = warp >> 1, wn = warp & 1;
    int mbase = wm * 32, nbase = wn * WN;

    float acc[2][NB][4];
#pragma unroll
    for (int mb = 0; mb < 2; mb++)
#pragma unroll
        for (int nb = 0; nb < NB; nb++)
#pragma unroll
            for (int q = 0; q < 4; q++) acc[mb][nb][q] = 0.f;

    unsigned aBase = (unsigned)__cvta_generic_to_shared(As);
    unsigned wBase = (unsigned)__cvta_generic_to_shared(Ws);

#pragma unroll
    for (int k0 = 0; k0 < K; k0 += 16) {
        unsigned a[2][4];
#pragma unroll
        for (int mb = 0; mb < 2; mb++) {
            int r = mbase + mb * 16 + (lane & 15);
            int ch = k0 + ((lane >> 4) << 3);
            unsigned addr = aBase + (r * AS + ch) * 2;
            asm volatile("ldmatrix.sync.aligned.m8n8.x4.shared.b16 {%0,%1,%2,%3}, [%4];"
                         : "=r"(a[mb][0]), "=r"(a[mb][1]), "=r"(a[mb][2]), "=r"(a[mb][3])
                         : "r"(addr));
        }
        unsigned b[NB][2];
#pragma unroll
        for (int nb16 = 0; nb16 < WN / 16; nb16++) {
            int kr = k0 + (lane & 15);
            int c = nbase + nb16 * 16 + ((lane >> 4) << 3);
            unsigned addr = wBase + (kr * WS + c) * 2;
            unsigned r0, r1, r2, r3;
            asm volatile("ldmatrix.sync.aligned.m8n8.x4.trans.shared.b16 {%0,%1,%2,%3}, [%4];"
                         : "=r"(r0), "=r"(r1), "=r"(r2), "=r"(r3)
                         : "r"(addr));
            b[nb16 * 2][0] = r0;     b[nb16 * 2][1] = r1;
            b[nb16 * 2 + 1][0] = r2; b[nb16 * 2 + 1][1] = r3;
        }
#pragma unroll
        for (int mb = 0; mb < 2; mb++)
#pragma unroll
            for (int nb = 0; nb < NB; nb++)
                asm volatile(
                    "mma.sync.aligned.m16n8k16.row.col.f32.f16.f16.f32 "
                    "{%0,%1,%2,%3}, {%4,%5,%6,%7}, {%8,%9}, {%0,%1,%2,%3};"
                    : "+f"(acc[mb][nb][0]), "+f"(acc[mb][nb][1]),
                      "+f"(acc[mb][nb][2]), "+f"(acc[mb][nb][3])
                    : "r"(a[mb][0]), "r"(a[mb][1]), "r"(a[mb][2]), "r"(a[mb][3]),
                      "r"(b[nb][0]), "r"(b[nb][1]));
    }

    int gq = lane >> 2, gc = (lane & 3) * 2;
#pragma unroll
    for (int mb = 0; mb < 2; mb++) {
        int ra = row0 + mbase + mb * 16 + gq;
        int rb = ra + 8;
#pragma unroll
        for (int nb = 0; nb < NB; nb++) {
            int col = nbase + nb * 8 + gc;
            if (ra < n) {
                __half2 p = __floats2half2_rn(acc[mb][nb][0], acc[mb][nb][1]);
                *(__half2*)(C + (size_t)ra * M + col) = p;
            }
            if (rb < n) {
                __half2 p = __floats2half2_rn(acc[mb][nb][2], acc[mb][nb][3]);
                *(__half2*)(C + (size_t)rb * M + col) = p;
            }
        }
    }
}

// ---------------- plain HMMA GEMM (layer 2) ----------
template <int K, int M, int WN>
__global__ __launch_bounds__(256, 2) void mma_gemm_kernel(
    const __half* __restrict__ A, const __half* __restrict__ W,
    __half* __restrict__ C, int n) {
    const int BM = 128;
    const int AS = K + 8, WS = M + 8, NB = WN / 8;
    extern __shared__ __half sm[];
    __half* As = sm;
    __half* Ws = sm + BM * AS;
    int tid = threadIdx.x;
    int row0 = blockIdx.x * BM;

    for (int i = tid; i < BM * K / 8; i += 256) {
        int r = i / (K / 8), c = i % (K / 8);
        uint4 v = (row0 + r < n) ? *(const uint4*)(A + (size_t)(row0 + r) * K + c * 8)
                                 : make_uint4(0, 0, 0, 0);
        *(uint4*)(As + r * AS + c * 8) = v;
    }
    for (int i = tid; i < K * M / 8; i += 256) {
        int r = i / (M / 8), c = i % (M / 8);
        *(uint4*)(Ws + r * WS + c * 8) = *(const uint4*)(W + r * M + c * 8);
    }
    __syncthreads();

    int warp = tid >> 5, lane = tid & 31;
    int wm = warp >> 1, wn = warp & 1;
    int mbase = wm * 32, nbase = wn * WN;

    float acc[2][NB][4];
#pragma unroll
    for (int mb = 0; mb < 2; mb++)
#pragma unroll
        for (int nb = 0; nb < NB; nb++)
#pragma unroll
            for (int q = 0; q < 4; q++) acc[mb][nb][q] = 0.f;

    unsigned aBase = (unsigned)__cvta_generic_to_shared(As);
    unsigned wBase = (unsigned)__cvta_generic_to_shared(Ws);

#pragma unroll
    for (int k0 = 0; k0 < K; k0 += 16) {
        unsigned a[2][4];
#pragma unroll
        for (int mb = 0; mb < 2; mb++) {
            int r = mbase + mb * 16 + (lane & 15);
            int ch = k0 + ((lane >> 4) << 3);
            unsigned addr = aBase + (r * AS + ch) * 2;
            asm volatile("ldmatrix.sync.aligned.m8n8.x4.shared.b16 {%0,%1,%2,%3}, [%4];"
                         : "=r"(a[mb][0]), "=r"(a[mb][1]), "=r"(a[mb][2]), "=r"(a[mb][3])
                         : "r"(addr));
        }
        unsigned b[NB][2];
#pragma unroll
        for (int nb16 = 0; nb16 < WN / 16; nb16++) {
            int kr = k0 + (lane & 15);
            int c = nbase + nb16 * 16 + ((lane >> 4) << 3);
            unsigned addr = wBase + (kr * WS + c) * 2;
            unsigned r0, r1, r2, r3;
            asm volatile("ldmatrix.sync.aligned.m8n8.x4.trans.shared.b16 {%0,%1,%2,%3}, [%4];"
                         : "=r"(r0), "=r"(r1), "=r"(r2), "=r"(r3)
                         : "r"(addr));
            b[nb16 * 2][0] = r0;     b[nb16 * 2][1] = r1;
            b[nb16 * 2 + 1][0] = r2; b[nb16 * 2 + 1][1] = r3;
        }
#pragma unroll
        for (int mb = 0; mb < 2; mb++)
#pragma unroll
            for (int nb = 0; nb < NB; nb++)
                asm volatile(
                    "mma.sync.aligned.m16n8k16.row.col.f32.f16.f16.f32 "
                    "{%0,%1,%2,%3}, {%4,%5,%6,%7}, {%8,%9}, {%0,%1,%2,%3};"
                    : "+f"(acc[mb][nb][0]), "+f"(acc[mb][nb][1]),
                      "+f"(acc[mb][nb][2]), "+f"(acc[mb][nb][3])
                    : "r"(a[mb][0]), "r"(a[mb][1]), "r"(a[mb][2]), "r"(a[mb][3]),
                      "r"(b[nb][0]), "r"(b[nb][1]));
    }

    int gq = lane >> 2, gc = (lane & 3) * 2;
#pragma unroll
    for (int mb = 0; mb < 2; mb++) {
        int ra = row0 + mbase + mb * 16 + gq;
        int rb = ra + 8;
#pragma unroll
        for (int nb = 0; nb < NB; nb++) {
            int col = nbase + nb * 8 + gc;
            if (ra < n) {
                __half2 p = __floats2half2_rn(acc[mb][nb][0], acc[mb][nb][1]);
                *(__half2*)(C + (size_t)ra * M + col) = p;
            }
            if (rb < n) {
                __half2 p = __floats2half2_rn(acc[mb][nb][2], acc[mb][nb][3]);
                *(__half2*)(C + (size_t)rb * M + col) = p;
            }
        }
    }
}

// -------------- aggregate: EP edges per iteration, uint4 row chunks, FFMA2 -----
// RL = lanes per row (8 halfs each); EP = 32/RL edges in flight.
// Lane layout: g = lane/RL (edge slot), q = lane%RL (16B chunk -> channels q*8..+7).
template <int C, bool L1>
__global__ void aggregate_kernel(const __half* __restrict__ h,
                                 const float2* __restrict__ as,
                                 const float2* __restrict__ ad,
                                 const int* __restrict__ counts,
                                 const int* __restrict__ adjp,
                                 const float* __restrict__ bias,
                                 __half* __restrict__ outh,
                                 float* __restrict__ outf,
                                 const float2* __restrict__ wa2s,
                                 const float2* __restrict__ wa2d,
                                 float2* __restrict__ as2, float2* __restrict__ ad2,
                                 int n) {
    const int RL = C / 4;          // 16 for C=64, 8 for C=32
    const int EP = 32 / RL;        // 2 / 4 edges per iteration
    const int HB = C / 8;          // head boundary in q units (8 / 4)
    int warp = (blockIdx.x * blockDim.x + threadIdx.x) >> 5;
    int lane = threadIdx.x & 31;
    if (warp >= n) return;

    int cnt = counts[warp];
    if (cnt > CAP) cnt = CAP;
    const int* abase = adjp + warp * CAP;
    float2 adv = ad[warp];
    int g = lane / RL;
    int q = lane % RL;
    bool hsel = q >= HB;           // this lane's channels belong to head1

    unsigned long long acc2[4] = {0ull, 0ull, 0ull, 0ull};
    float d0 = 0.f, d1 = 0.f;
    const __half* hq = h + q * 8;

    for (int chunk = 0; chunk < cnt; chunk += 32) {
        int cn = cnt - chunk;
        if (cn > 32) cn = 32;
        int s = 0; float w0 = 0.f, w1 = 0.f;
        if (lane < cn) {
            s = abase[chunk + lane];
            float2 a = as[s];
            w0 = __expf(lrelu(a.x + adv.x));
            w1 = __expf(lrelu(a.y + adv.y));
        }
        d0 += w0; d1 += w1;

        for (int t = 0; t < cn; t += EP) {
            int idx = t + g;       // my edge slot (w=0 beyond cn -> contributes 0)
            int se = __shfl_sync(0xffffffffu, s, idx);
            float wa = __shfl_sync(0xffffffffu, w0, idx);
            float wb = __shfl_sync(0xffffffffu, w1, idx);
            float we = hsel ? wb : wa;
            unsigned long long w2 = pack2(we, we);
            uint4 r = *(const uint4*)(hq + (size_t)se * (2 * C));
            float2 f0 = __half22float2(*(__half2*)&r.x);
            float2 f1 = __half22float2(*(__half2*)&r.y);
            float2 f2 = __half22float2(*(__half2*)&r.z);
            float2 f3 = __half22float2(*(__half2*)&r.w);
            ffma2(acc2[0], w2, pack2(f0.x, f0.y));
            ffma2(acc2[1], w2, pack2(f1.x, f1.y));
            ffma2(acc2[2], w2, pack2(f2.x, f2.y));
            ffma2(acc2[3], w2, pack2(f3.x, f3.y));
        }
    }

    float acc[8];
#pragma unroll
    for (int j = 0; j < 4; j++) {
        float2 f = unpack2(acc2[j]);
        acc[2 * j] = f.x; acc[2 * j + 1] = f.y;
    }
    // combine edge slots (lanes with same q, different g)
#pragma unroll
    for (int off = RL; off < 32; off <<= 1)
#pragma unroll
        for (int j = 0; j < 8; j++)
            acc[j] += __shfl_xor_sync(0xffffffffu, acc[j], off);
    // denominators over all 32 lanes
#pragma unroll
    for (int off = 16; off >= 1; off >>= 1) {
        d0 += __shfl_xor_sync(0xffffffffu, d0, off);
        d1 += __shfl_xor_sync(0xffffffffu, d1, off);
    }
    float dm = (hsel ? d1 : d0) + 1e-16f;

    float res[8];
#pragma unroll
    for (int j = 0; j < 8; j++) {
        float xv = acc[j] / dm;
        float yv = __shfl_xor_sync(0xffffffffu, xv, HB);  // partner-head channel
        res[j] = 0.5f * (xv + yv);
    }

    bool valid = (g == 0) && !hsel;   // lanes holding final channels q*8..q*8+7
    int c0 = q * 8;

    if (L1) {
        float p0 = 0, p1 = 0, p2 = 0, p3 = 0;
        if (valid) {
#pragma unroll
            for (int j = 0; j < 8; j++) {
                float v = res[j] + bias[c0 + j];
                v = v > 0.f ? v : expm1f(v);
                res[j] = v;
            }
            __half2 o0 = __floats2half2_rn(res[0], res[1]);
            __half2 o1 = __floats2half2_rn(res[2], res[3]);
            __half2 o2 = __floats2half2_rn(res[4], res[5]);
            __half2 o3 = __floats2half2_rn(res[6], res[7]);
            *(uint4*)(outh + (size_t)warp * 64 + c0) = make_uint4(
                *(unsigned*)&o0, *(unsigned*)&o1, *(unsigned*)&o2, *(unsigned*)&o3);
#pragma unroll
            for (int j = 0; j < 8; j++) {
                float2 ws = wa2s[c0 + j], wd = wa2d[c0 + j];
                p0 = fmaf(res[j], ws.x, p0); p1 = fmaf(res[j], ws.y, p1);
                p2 = fmaf(res[j], wd.x, p2); p3 = fmaf(res[j], wd.y, p3);
            }
        }
        // sum partial dots across lanes 0..HB-1 (xor stays within the aligned group)
#pragma unroll
        for (int off = 1; off < HB; off <<= 1) {
            p0 += __shfl_xor_sync(0xffffffffu, p0, off);
            p1 += __shfl_xor_sync(0xffffffffu, p1, off);
            p2 += __shfl_xor_sync(0xffffffffu, p2, off);
            p3 += __shfl_xor_sync(0xffffffffu, p3, off);
        }
        if (lane == 0) {
            as2[warp] = make_float2(p0, p1);
            ad2[warp] = make_float2(p2, p3);
        }
    } else {
        if (valid) {
#pragma unroll
            for (int j = 0; j < 8; j++) res[j] += bias[c0 + j];
            float* op = outf + (size_t)warp * C + c0;
            *(float4*)op = make_float4(res[0], res[1], res[2], res[3]);
            *(float4*)(op + 4) = make_float4(res[4], res[5], res[6], res[7]);
        }
    }
}

// ---------------------------- launch ----------------------------
extern "C" void kernel_launch(void* const* d_in, const int* in_sizes, int n_in,
                              void* d_out, int out_size) {
    const float* x    = (const float*)d_in[0];
    const int*   ei   = (const int*)d_in[1];
    const float* W1   = (const float*)d_in[2];
    const float* as1w = (const float*)d_in[3];
    const float* ad1w = (const float*)d_in[4];
    const float* b1   = (const float*)d_in[5];
    const float* W2   = (const float*)d_in[6];
    const float* as2w = (const float*)d_in[7];
    const float* ad2w = (const float*)d_in[8];
    const float* b2   = (const float*)d_in[9];
    float* out = (float*)d_out;

    int N = in_sizes[0] / 128;
    int E = in_sizes[1] / 2;
    if (N > NMAX) N = NMAX;
    int Etot = E + N;

    __half *h1, *hfh, *h2, *W1h, *W2h;
    float2 *wa1s, *wa1d, *wa2s, *wa2d;
    float2 *pas1, *pad1, *pas2, *pad2;
    int *cursor, *adjp;
    cudaGetSymbolAddress((void**)&h1,   g_h1);
    cudaGetSymbolAddress((void**)&hfh,  g_hfh);
    cudaGetSymbolAddress((void**)&h2,   g_h2);
    cudaGetSymbolAddress((void**)&W1h,  g_W1h);
    cudaGetSymbolAddress((void**)&W2h,  g_W2h);
    cudaGetSymbolAddress((void**)&wa1s, g_wa1s);
    cudaGetSymbolAddress((void**)&wa1d, g_wa1d);
    cudaGetSymbolAddress((void**)&wa2s, g_wa2s);
    cudaGetSymbolAddress((void**)&wa2d, g_wa2d);
    cudaGetSymbolAddress((void**)&pas1, g_as1);
    cudaGetSymbolAddress((void**)&pad1, g_ad1);
    cudaGetSymbolAddress((void**)&pas2, g_as2);
    cudaGetSymbolAddress((void**)&pad2, g_ad2);
    cudaGetSymbolAddress((void**)&cursor, g_cursor);
    cudaGetSymbolAddress((void**)&adjp,   g_adjp);

    const int SM1 = (128 * 136 + 128 * 136) * 2 + 128 * 16;
    const int SM2 = (128 * 72 + 64 * 72) * 2;
    cudaFuncSetAttribute((const void*)mma_gemm1_fused_kernel,
                         cudaFuncAttributeMaxDynamicSharedMemorySize, SM1);
    cudaFuncSetAttribute((const void*)mma_gemm_kernel<64, 64, 32>,
                         cudaFuncAttributeMaxDynamicSharedMemorySize, SM2);

    int warpGrid = (N * 32 + 255) / 256;

    cudaMemsetAsync(cursor, 0, N * sizeof(int));
    fold_kernel<<<1, 256>>>(W1, as1w, ad1w, W2, as2w, ad2w,
                            W1h, W2h, wa1s, wa1d, wa2s, wa2d);
    scatter_kernel<<<(Etot + 255) / 256, 256>>>(ei, E, N, cursor, adjp);
    mma_gemm1_fused_kernel<<<(N + 127) / 128, 256, SM1>>>(
        x, W1h, wa1s, wa1d, h1, pas1, pad1, N);
    // profiled slot: layer-1 aggregate
    aggregate_kernel<64, true><<<warpGrid, 256>>>(h1, pas1, pad1, cursor, adjp, b1,
                                                  hfh, nullptr, wa2s, wa2d, pas2, pad2, N);
    mma_gemm_kernel<64, 64, 32><<<(N + 127) / 128, 256, SM2>>>(hfh, W2h, h2, N);
    aggregate_kernel<32, false><<<warpGrid, 256>>>(h2, pas2, pad2, cursor, adjp, b2,
                                                   nullptr, out, nullptr, nullptr,
                                                   nullptr, nullptr, N);
}

// round 13
// speedup vs baseline: 1.0025x; 1.0025x over previous
#include <cuda_runtime.h>
#include <cuda_fp16.h>
#include <math.h>

// ---------------- problem-size caps (compile-time scratch) ----------------
#define NMAX 100000
#define EMAX 1700000
#define CAP  96        // max padded degree (Poisson(16)+1; overflow prob ~1e-20)

// ---------------- device scratch (no allocations allowed) -----------------
__device__ __half  g_h1[NMAX * 128];   // layer1 features fp16 [N, 2*64]
__device__ __half  g_hfh[NMAX * 64];   // layer1 output (elu) fp16 [N, 64]
__device__ __half  g_h2[NMAX * 64];    // layer2 features fp16 [N, 2*32]
__device__ __half  g_W1h[128 * 128];
__device__ __half  g_W2h[64 * 64];
__device__ float2  g_wa1s[128], g_wa1d[128];   // folded W@att per k (h0,h1)
__device__ float2  g_wa2s[64],  g_wa2d[64];
__device__ float2  g_as1[NMAX], g_ad1[NMAX];
__device__ float2  g_as2[NMAX], g_ad2[NMAX];
__device__ int     g_cursor[NMAX];             // per-dst degree counter
__device__ int     g_adjp[NMAX * CAP];         // padded adjacency buckets

__device__ __forceinline__ float lrelu(float x) { return x > 0.f ? x : 0.2f * x; }

// ---- packed f32x2 helpers ----
__device__ __forceinline__ unsigned long long pack2(float lo, float hi) {
    unsigned long long r;
    asm("mov.b64 %0, {%1, %2};" : "=l"(r) : "f"(lo), "f"(hi));
    return r;
}
__device__ __forceinline__ void ffma2(unsigned long long& d, unsigned long long a,
                                      unsigned long long b) {
    asm("fma.rn.f32x2 %0, %1, %2, %0;" : "+l"(d) : "l"(a), "l"(b));
}
__device__ __forceinline__ float2 unpack2(unsigned long long v) {
    float2 r;
    asm("mov.b64 {%0, %1}, %2;" : "=f"(r.x), "=f"(r.y) : "l"(v));
    return r;
}

// ---------------- fold: wa = W @ att (per head) + fp16 weight conversion -------
__global__ void fold_kernel(const float* __restrict__ W1, const float* __restrict__ as1,
                            const float* __restrict__ ad1,
                            const float* __restrict__ W2, const float* __restrict__ as2,
                            const float* __restrict__ ad2,
                            __half* W1h, __half* W2h,
                            float2* wa1s, float2* wa1d, float2* wa2s, float2* wa2d) {
    int t = threadIdx.x;  // 256 threads, 1 block
    for (int i = t; i < 128 * 128; i += 256) W1h[i] = __float2half(W1[i]);
    for (int i = t; i < 64 * 64; i += 256)   W2h[i] = __float2half(W2[i]);
    if (t < 128) {
        float s0 = 0, s1 = 0, d0 = 0, d1 = 0;
        for (int c = 0; c < 64; c++) {
            float w0 = W1[t * 128 + c], w1 = W1[t * 128 + 64 + c];
            s0 = fmaf(w0, as1[c], s0);      s1 = fmaf(w1, as1[64 + c], s1);
            d0 = fmaf(w0, ad1[c], d0);      d1 = fmaf(w1, ad1[64 + c], d1);
        }
        wa1s[t] = make_float2(s0, s1); wa1d[t] = make_float2(d0, d1);
    }
    if (t < 64) {
        float s0 = 0, s1 = 0, d0 = 0, d1 = 0;
        for (int c = 0; c < 32; c++) {
            float w0 = W2[t * 64 + c], w1 = W2[t * 64 + 32 + c];
            s0 = fmaf(w0, as2[c], s0);      s1 = fmaf(w1, as2[32 + c], s1);
            d0 = fmaf(w0, ad2[c], d0);      d1 = fmaf(w1, ad2[32 + c], d1);
        }
        wa2s[t] = make_float2(s0, s1); wa2d[t] = make_float2(d0, d1);
    }
}

// ---------------- padded-bucket scatter ----------------
__global__ void scatter_kernel(const int* __restrict__ ei, int E, int N,
                               int* cursor, int* __restrict__ adjp) {
    int e = blockIdx.x * blockDim.x + threadIdx.x;
    int tot = E + N;
    if (e >= tot) return;
    int src, dst;
    if (e < E) { src = ei[e]; dst = ei[E + e]; }
    else       { src = e - E; dst = e - E; }
    int pos = atomicAdd(&cursor[dst], 1);
    if (pos < CAP) adjp[dst * CAP + pos] = src;
}

// ---------- fused GEMM1: fp32 x -> fp16 convert + HMMA + exact as1/ad1 ----------
__global__ __launch_bounds__(256, 2) void mma_gemm1_fused_kernel(
    const float* __restrict__ X, const __half* __restrict__ W,
    const float2* __restrict__ wa1s, const float2* __restrict__ wa1d,
    __half* __restrict__ C, float2* __restrict__ as, float2* __restrict__ ad, int n) {
    const int K = 128, M = 128, WN = 64, BM = 128;
    const int AS = K + 8, WS = M + 8, NB = WN / 8;
    extern __shared__ __half sm[];
    __half* As = sm;
    __half* Ws = sm + BM * AS;
    float4* sWa = (float4*)(Ws + K * WS);
    int tid = threadIdx.x;
    int lane = tid & 31;
    int row0 = blockIdx.x * BM;

    if (tid < 128) {
        float2 ws = wa1s[tid], wd = wa1d[tid];
        sWa[tid] = make_float4(ws.x, ws.y, wd.x, wd.y);
    }
    for (int i = tid; i < K * M / 8; i += 256) {
        int r = i / (M / 8), c = i % (M / 8);
        *(uint4*)(Ws + r * WS + c * 8) = *(const uint4*)(W + r * M + c * 8);
    }
    __syncthreads();

    const float4* X4 = (const float4*)X;
#pragma unroll
    for (int jj = 0; jj < BM * K / 8 / 256; jj++) {
        int i = tid + jj * 256;
        int r = i >> 4, c = i & 15;
        int row = row0 + r;
        float4 v0, v1;
        if (row < n) {
            v0 = X4[(size_t)row * 32 + c * 2];
            v1 = X4[(size_t)row * 32 + c * 2 + 1];
        } else {
            v0 = make_float4(0, 0, 0, 0); v1 = v0;
        }
        __half2 p0 = __floats2half2_rn(v0.x, v0.y), p1 = __floats2half2_rn(v0.z, v0.w);
        __half2 p2 = __floats2half2_rn(v1.x, v1.y), p3 = __floats2half2_rn(v1.z, v1.w);
        *(uint4*)(As + r * AS + c * 8) = make_uint4(
            *(unsigned*)&p0, *(unsigned*)&p1, *(unsigned*)&p2, *(unsigned*)&p3);

        float xs[8] = {v0.x, v0.y, v0.z, v0.w, v1.x, v1.y, v1.z, v1.w};
        float s0 = 0, s1 = 0, d0 = 0, d1 = 0;
        int k0 = c * 8;
#pragma unroll
        for (int e = 0; e < 8; e++) {
            float4 w = sWa[k0 + e];
            s0 = fmaf(xs[e], w.x, s0); s1 = fmaf(xs[e], w.y, s1);
            d0 = fmaf(xs[e], w.z, d0); d1 = fmaf(xs[e], w.w, d1);
        }
#pragma unroll
        for (int off = 8; off >= 1; off >>= 1) {
            s0 += __shfl_xor_sync(0xffffffffu, s0, off);
            s1 += __shfl_xor_sync(0xffffffffu, s1, off);
            d0 += __shfl_xor_sync(0xffffffffu, d0, off);
            d1 += __shfl_xor_sync(0xffffffffu, d1, off);
        }
        if ((lane & 15) == 0 && row < n) {
            as[row] = make_float2(s0, s1);
            ad[row] = make_float2(d0, d1);
        }
    }
    __syncthreads();

    int warp = tid >> 5;
    int wm = warp >> 1, wn = warp & 1;
    int mbase = wm * 32, nbase = wn * WN;

    float acc[2][NB][4];
#pragma unroll
    for (int mb = 0; mb < 2; mb++)
#pragma unroll
        for (int nb = 0; nb < NB; nb++)
#pragma unroll
            for (int q = 0; q < 4; q++) acc[mb][nb][q] = 0.f;

    unsigned aBase = (unsigned)__cvta_generic_to_shared(As);
    unsigned wBase = (unsigned)__cvta_generic_to_shared(Ws);

#pragma unroll
    for (int k0 = 0; k0 < K; k0 += 16) {
        unsigned a[2][4];
#pragma unroll
        for (int mb = 0; mb < 2; mb++) {
            int r = mbase + mb * 16 + (lane & 15);
            int ch = k0 + ((lane >> 4) << 3);
            unsigned addr = aBase + (r * AS + ch) * 2;
            asm volatile("ldmatrix.sync.aligned.m8n8.x4.shared.b16 {%0,%1,%2,%3}, [%4];"
                         : "=r"(a[mb][0]), "=r"(a[mb][1]), "=r"(a[mb][2]), "=r"(a[mb][3])
                         : "r"(addr));
        }
        unsigned b[NB][2];
#pragma unroll
        for (int nb16 = 0; nb16 < WN / 16; nb16++) {
            int kr = k0 + (lane & 15);
            int c = nbase + nb16 * 16 + ((lane >> 4) << 3);
            unsigned addr = wBase + (kr * WS + c) * 2;
            unsigned r0, r1, r2, r3;
            asm volatile("ldmatrix.sync.aligned.m8n8.x4.trans.shared.b16 {%0,%1,%2,%3}, [%4];"
                         : "=r"(r0), "=r"(r1), "=r"(r2), "=r"(r3)
                         : "r"(addr));
            b[nb16 * 2][0] = r0;     b[nb16 * 2][1] = r1;
            b[nb16 * 2 + 1][0] = r2; b[nb16 * 2 + 1][1] = r3;
        }
#pragma unroll
        for (int mb = 0; mb < 2; mb++)
#pragma unroll
            for (int nb = 0; nb < NB; nb++)
                asm volatile(
                    "mma.sync.aligned.m16n8k16.row.col.f32.f16.f16.f32 "
                    "{%0,%1,%2,%3}, {%4,%5,%6,%7}, {%8,%9}, {%0,%1,%2,%3};"
                    : "+f"(acc[mb][nb][0]), "+f"(acc[mb][nb][1]),
                      "+f"(acc[mb][nb][2]), "+f"(acc[mb][nb][3])
                    : "r"(a[mb][0]), "r"(a[mb][1]), "r"(a[mb][2]), "r"(a[mb][3]),
                      "r"(b[nb][0]), "r"(b[nb][1]));
    }

    int gq = lane >> 2, gc = (lane & 3) * 2;
#pragma unroll
    for (int mb = 0; mb < 2; mb++) {
        int ra = row0 + mbase + mb * 16 + gq;
        int rb = ra + 8;
#pragma unroll
        for (int nb = 0; nb < NB; nb++) {
            int col = nbase + nb * 8 + gc;
            if (ra < n) {
                __half2 p = __floats2half2_rn(acc[mb][nb][0], acc[mb][nb][1]);
                *(__half2*)(C + (size_t)ra * M + col) = p;
            }
            if (rb < n) {
                __half2 p = __floats2half2_rn(acc[mb][nb][2], acc[mb][nb][3]);
                *(__half2*)(C + (size_t)rb * M + col) = p;
            }
        }
    }
}

// ---------------- plain HMMA GEMM (layer 2) ----------
template <int K, int M, int WN>
__global__ __launch_bounds__(256, 2) void mma_gemm_kernel(
    const __half* __restrict__ A, const __half* __restrict__ W,
    __half* __restrict__ C, int n) {
    const int BM = 128;
    const int AS = K + 8, WS = M + 8, NB = WN / 8;
    extern __shared__ __half sm[];
    __half* As = sm;
    __half* Ws = sm + BM * AS;
    int tid = threadIdx.x;
    int row0 = blockIdx.x * BM;

    for (int i = tid; i < BM * K / 8; i += 256) {
        int r = i / (K / 8), c = i % (K / 8);
        uint4 v = (row0 + r < n) ? *(const uint4*)(A + (size_t)(row0 + r) * K + c * 8)
                                 : make_uint4(0, 0, 0, 0);
        *(uint4*)(As + r * AS + c * 8) = v;
    }
    for (int i = tid; i < K * M / 8; i += 256) {
        int r = i / (M / 8), c = i % (M / 8);
        *(uint4*)(Ws + r * WS + c * 8) = *(const uint4*)(W + r * M + c * 8);
    }
    __syncthreads();

    int warp = tid >> 5, lane = tid & 31;
    int wm = warp >> 1, wn = warp & 1;
    int mbase = wm * 32, nbase = wn * WN;

    float acc[2][NB][4];
#pragma unroll
    for (int mb = 0; mb < 2; mb++)
#pragma unroll
        for (int nb = 0; nb < NB; nb++)
#pragma unroll
            for (int q = 0; q < 4; q++) acc[mb][nb][q] = 0.f;

    unsigned aBase = (unsigned)__cvta_generic_to_shared(As);
    unsigned wBase = (unsigned)__cvta_generic_to_shared(Ws);

#pragma unroll
    for (int k0 = 0; k0 < K; k0 += 16) {
        unsigned a[2][4];
#pragma unroll
        for (int mb = 0; mb < 2; mb++) {
            int r = mbase + mb * 16 + (lane & 15);
            int ch = k0 + ((lane >> 4) << 3);
            unsigned addr = aBase + (r * AS + ch) * 2;
            asm volatile("ldmatrix.sync.aligned.m8n8.x4.shared.b16 {%0,%1,%2,%3}, [%4];"
                         : "=r"(a[mb][0]), "=r"(a[mb][1]), "=r"(a[mb][2]), "=r"(a[mb][3])
                         : "r"(addr));
        }
        unsigned b[NB][2];
#pragma unroll
        for (int nb16 = 0; nb16 < WN / 16; nb16++) {
            int kr = k0 + (lane & 15);
            int c = nbase + nb16 * 16 + ((lane >> 4) << 3);
            unsigned addr = wBase + (kr * WS + c) * 2;
            unsigned r0, r1, r2, r3;
            asm volatile("ldmatrix.sync.aligned.m8n8.x4.trans.shared.b16 {%0,%1,%2,%3}, [%4];"
                         : "=r"(r0), "=r"(r1), "=r"(r2), "=r"(r3)
                         : "r"(addr));
            b[nb16 * 2][0] = r0;     b[nb16 * 2][1] = r1;
            b[nb16 * 2 + 1][0] = r2; b[nb16 * 2 + 1][1] = r3;
        }
#pragma unroll
        for (int mb = 0; mb < 2; mb++)
#pragma unroll
            for (int nb = 0; nb < NB; nb++)
                asm volatile(
                    "mma.sync.aligned.m16n8k16.row.col.f32.f16.f16.f32 "
                    "{%0,%1,%2,%3}, {%4,%5,%6,%7}, {%8,%9}, {%0,%1,%2,%3};"
                    : "+f"(acc[mb][nb][0]), "+f"(acc[mb][nb][1]),
                      "+f"(acc[mb][nb][2]), "+f"(acc[mb][nb][3])
                    : "r"(a[mb][0]), "r"(a[mb][1]), "r"(a[mb][2]), "r"(a[mb][3]),
                      "r"(b[nb][0]), "r"(b[nb][1]));
    }

    int gq = lane >> 2, gc = (lane & 3) * 2;
#pragma unroll
    for (int mb = 0; mb < 2; mb++) {
        int ra = row0 + mbase + mb * 16 + gq;
        int rb = ra + 8;
#pragma unroll
        for (int nb = 0; nb < NB; nb++) {
            int col = nbase + nb * 8 + gc;
            if (ra < n) {
                __half2 p = __floats2half2_rn(acc[mb][nb][0], acc[mb][nb][1]);
                *(__half2*)(C + (size_t)ra * M + col) = p;
            }
            if (rb < n) {
                __half2 p = __floats2half2_rn(acc[mb][nb][2], acc[mb][nb][3]);
                *(__half2*)(C + (size_t)rb * M + col) = p;
            }
        }
    }
}

// -------------- aggregate: EP edges per iteration, uint4 row chunks, FFMA2 -----
// RL = lanes per row (8 halfs each); EP = 32/RL edges in flight.
// Lane layout: g = lane/RL (edge slot), q = lane%RL (16B chunk -> channels q*8..+7).
template <int C, bool L1>
__global__ void aggregate_kernel(const __half* __restrict__ h,
                                 const float2* __restrict__ as,
                                 const float2* __restrict__ ad,
                                 const int* __restrict__ counts,
                                 const int* __restrict__ adjp,
                                 const float* __restrict__ bias,
                                 __half* __restrict__ outh,
                                 float* __restrict__ outf,
                                 const float2* __restrict__ wa2s,
                                 const float2* __restrict__ wa2d,
                                 float2* __restrict__ as2, float2* __restrict__ ad2,
                                 int n) {
    const int RL = C / 4;          // 16 for C=64, 8 for C=32
    const int EP = 32 / RL;        // 2 / 4 edges per iteration
    const int HB = C / 8;          // head boundary in q units (8 / 4)
    int warp = (blockIdx.x * blockDim.x + threadIdx.x) >> 5;
    int lane = threadIdx.x & 31;
    if (warp >= n) return;

    int cnt = counts[warp];
    if (cnt > CAP) cnt = CAP;
    const int* abase = adjp + warp * CAP;
    float2 adv = ad[warp];
    int g = lane / RL;
    int q = lane % RL;
    bool hsel = q >= HB;           // this lane's channels belong to head1

    unsigned long long acc2[4] = {0ull, 0ull, 0ull, 0ull};
    float d0 = 0.f, d1 = 0.f;
    const __half* hq = h + q * 8;

    for (int chunk = 0; chunk < cnt; chunk += 32) {
        int cn = cnt - chunk;
        if (cn > 32) cn = 32;
        int s = 0; float w0 = 0.f, w1 = 0.f;
        if (lane < cn) {
            s = abase[chunk + lane];
            float2 a = as[s];
            w0 = __expf(lrelu(a.x + adv.x));
            w1 = __expf(lrelu(a.y + adv.y));
        }
        d0 += w0; d1 += w1;

        for (int t = 0; t < cn; t += EP) {
            int idx = t + g;       // my edge slot (w=0 beyond cn -> contributes 0)
            int se = __shfl_sync(0xffffffffu, s, idx);
            float wa = __shfl_sync(0xffffffffu, w0, idx);
            float wb = __shfl_sync(0xffffffffu, w1, idx);
            float we = hsel ? wb : wa;
            unsigned long long w2 = pack2(we, we);
            uint4 r = *(const uint4*)(hq + (size_t)se * (2 * C));
            float2 f0 = __half22float2(*(__half2*)&r.x);
            float2 f1 = __half22float2(*(__half2*)&r.y);
            float2 f2 = __half22float2(*(__half2*)&r.z);
            float2 f3 = __half22float2(*(__half2*)&r.w);
            ffma2(acc2[0], w2, pack2(f0.x, f0.y));
            ffma2(acc2[1], w2, pack2(f1.x, f1.y));
            ffma2(acc2[2], w2, pack2(f2.x, f2.y));
            ffma2(acc2[3], w2, pack2(f3.x, f3.y));
        }
    }

    float acc[8];
#pragma unroll
    for (int j = 0; j < 4; j++) {
        float2 f = unpack2(acc2[j]);
        acc[2 * j] = f.x; acc[2 * j + 1] = f.y;
    }
    // combine edge slots (lanes with same q, different g)
#pragma unroll
    for (int off = RL; off < 32; off <<= 1)
#pragma unroll
        for (int j = 0; j < 8; j++)
            acc[j] += __shfl_xor_sync(0xffffffffu, acc[j], off);
    // denominators over all 32 lanes
#pragma unroll
    for (int off = 16; off >= 1; off >>= 1) {
        d0 += __shfl_xor_sync(0xffffffffu, d0, off);
        d1 += __shfl_xor_sync(0xffffffffu, d1, off);
    }
    float dm = (hsel ? d1 : d0) + 1e-16f;

    float res[8];
#pragma unroll
    for (int j = 0; j < 8; j++) {
        float xv = acc[j] / dm;
        float yv = __shfl_xor_sync(0xffffffffu, xv, HB);  // partner-head channel
        res[j] = 0.5f * (xv + yv);
    }

    bool valid = (g == 0) && !hsel;   // lanes holding final channels q*8..q*8+7
    int c0 = q * 8;

    if (L1) {
        float p0 = 0, p1 = 0, p2 = 0, p3 = 0;
        if (valid) {
#pragma unroll
            for (int j = 0; j < 8; j++) {
                float v = res[j] + bias[c0 + j];
                v = v > 0.f ? v : expm1f(v);
                res[j] = v;
            }
            __half2 o0 = __floats2half2_rn(res[0], res[1]);
            __half2 o1 = __floats2half2_rn(res[2], res[3]);
            __half2 o2 = __floats2half2_rn(res[4], res[5]);
            __half2 o3 = __floats2half2_rn(res[6], res[7]);
            *(uint4*)(outh + (size_t)warp * 64 + c0) = make_uint4(
                *(unsigned*)&o0, *(unsigned*)&o1, *(unsigned*)&o2, *(unsigned*)&o3);
#pragma unroll
            for (int j = 0; j < 8; j++) {
                float2 ws = wa2s[c0 + j], wd = wa2d[c0 + j];
                p0 = fmaf(res[j], ws.x, p0); p1 = fmaf(res[j], ws.y, p1);
                p2 = fmaf(res[j], wd.x, p2); p3 = fmaf(res[j], wd.y, p3);
            }
        }
        // sum partial dots across lanes 0..HB-1 (xor stays within the aligned group)
#pragma unroll
        for (int off = 1; off < HB; off <<= 1) {
            p0 += __shfl_xor_sync(0xffffffffu, p0, off);
            p1 += __shfl_xor_sync(0xffffffffu, p1, off);
            p2 += __shfl_xor_sync(0xffffffffu, p2, off);
            p3 += __shfl_xor_sync(0xffffffffu, p3, off);
        }
        if (lane == 0) {
            as2[warp] = make_float2(p0, p1);
            ad2[warp] = make_float2(p2, p3);
        }
    } else {
        if (valid) {
#pragma unroll
            for (int j = 0; j < 8; j++) res[j] += bias[c0 + j];
            float* op = outf + (size_t)warp * C + c0;
            *(float4*)op = make_float4(res[0], res[1], res[2], res[3]);
            *(float4*)(op + 4) = make_float4(res[4], res[5], res[6], res[7]);
        }
    }
}

// ---------------------------- launch ----------------------------
extern "C" void kernel_launch(void* const* d_in, const int* in_sizes, int n_in,
                              void* d_out, int out_size) {
    const float* x    = (const float*)d_in[0];
    const int*   ei   = (const int*)d_in[1];
    const float* W1   = (const float*)d_in[2];
    const float* as1w = (const float*)d_in[3];
    const float* ad1w = (const float*)d_in[4];
    const float* b1   = (const float*)d_in[5];
    const float* W2   = (const float*)d_in[6];
    const float* as2w = (const float*)d_in[7];
    const float* ad2w = (const float*)d_in[8];
    const float* b2   = (const float*)d_in[9];
    float* out = (float*)d_out;

    int N = in_sizes[0] / 128;
    int E = in_sizes[1] / 2;
    if (N > NMAX) N = NMAX;
    int Etot = E + N;

    __half *h1, *hfh, *h2, *W1h, *W2h;
    float2 *wa1s, *wa1d, *wa2s, *wa2d;
    float2 *pas1, *pad1, *pas2, *pad2;
    int *cursor, *adjp;
    cudaGetSymbolAddress((void**)&h1,   g_h1);
    cudaGetSymbolAddress((void**)&hfh,  g_hfh);
    cudaGetSymbolAddress((void**)&h2,   g_h2);
    cudaGetSymbolAddress((void**)&W1h,  g_W1h);
    cudaGetSymbolAddress((void**)&W2h,  g_W2h);
    cudaGetSymbolAddress((void**)&wa1s, g_wa1s);
    cudaGetSymbolAddress((void**)&wa1d, g_wa1d);
    cudaGetSymbolAddress((void**)&wa2s, g_wa2s);
    cudaGetSymbolAddress((void**)&wa2d, g_wa2d);
    cudaGetSymbolAddress((void**)&pas1, g_as1);
    cudaGetSymbolAddress((void**)&pad1, g_ad1);
    cudaGetSymbolAddress((void**)&pas2, g_as2);
    cudaGetSymbolAddress((void**)&pad2, g_ad2);
    cudaGetSymbolAddress((void**)&cursor, g_cursor);
    cudaGetSymbolAddress((void**)&adjp,   g_adjp);

    const int SM1 = (128 * 136 + 128 * 136) * 2 + 128 * 16;
    const int SM2 = (128 * 72 + 64 * 72) * 2;
    cudaFuncSetAttribute((const void*)mma_gemm1_fused_kernel,
                         cudaFuncAttributeMaxDynamicSharedMemorySize, SM1);
    cudaFuncSetAttribute((const void*)mma_gemm_kernel<64, 64, 32>,
                         cudaFuncAttributeMaxDynamicSharedMemorySize, SM2);

    int warpGrid = (N * 32 + 255) / 256;

    cudaMemsetAsync(cursor, 0, N * sizeof(int));
    fold_kernel<<<1, 256>>>(W1, as1w, ad1w, W2, as2w, ad2w,
                            W1h, W2h, wa1s, wa1d, wa2s, wa2d);
    scatter_kernel<<<(Etot + 255) / 256, 256>>>(ei, E, N, cursor, adjp);
    mma_gemm1_fused_kernel<<<(N + 127) / 128, 256, SM1>>>(
        x, W1h, wa1s, wa1d, h1, pas1, pad1, N);
    // profiled slot: layer-1 aggregate
    aggregate_kernel<64, true><<<warpGrid, 256>>>(h1, pas1, pad1, cursor, adjp, b1,
                                                  hfh, nullptr, wa2s, wa2d, pas2, pad2, N);
    mma_gemm_kernel<64, 64, 32><<<(N + 127) / 128, 256, SM2>>>(hfh, W2h, h2, N);
    aggregate_kernel<32, false><<<warpGrid, 256>>>(h2, pas2, pad2, cursor, adjp, b2,
                                                   nullptr, out, nullptr, nullptr,
                                                   nullptr, nullptr, N);
}